// round 5
// baseline (speedup 1.0000x reference)
#include <cuda_runtime.h>

#define D 128
#define N_NODES_MAX 50000
#define E_MAX 600000

// Scratch (device globals — no allocation allowed)
__device__ float g_h[N_NODES_MAX * D];      // h = x @ W^T
__device__ float g_ssrc[N_NODES_MAX];       // h @ a[:128]
__device__ float g_sdst[N_NODES_MAX];       // h @ a[128:]
__device__ int   g_cnt[N_NODES_MAX];        // in-degree histogram (ZERO invariant: zeroed at
                                            // module load; re-zeroed by scan_add each call)
__device__ int   g_off[N_NODES_MAX + 1];    // CSR offsets (by dst)
__device__ int   g_cursor[N_NODES_MAX];     // scatter cursors
__device__ int   g_bsum[64];                // per-1024-chunk sums
__device__ int   g_srcs[E_MAX];             // src ids sorted by dst

// ---------------- packed f32x2 helpers (sm_103a FFMA2) ----------------
__device__ __forceinline__ unsigned long long dup2(float v) {
    unsigned long long r;
    asm("mov.b64 %0, {%1, %1};" : "=l"(r) : "f"(v));
    return r;
}
__device__ __forceinline__ void fma2(unsigned long long& d, unsigned long long a,
                                     unsigned long long b) {
    asm("fma.rn.f32x2 %0, %1, %2, %0;" : "+l"(d) : "l"(a), "l"(b));
}
__device__ __forceinline__ float2 unpk2(unsigned long long v) {
    float2 f;
    asm("mov.b64 {%0, %1}, %2;" : "=f"(f.x), "=f"(f.y) : "l"(v));
    return f;
}
// L2-only (no L1 allocate) float4 / float loads
__device__ __forceinline__ float4 ldcg4(const float* p) {
    float4 v;
    asm("ld.global.cg.v4.f32 {%0, %1, %2, %3}, [%4];"
        : "=f"(v.x), "=f"(v.y), "=f"(v.z), "=f"(v.w) : "l"(p));
    return v;
}
__device__ __forceinline__ float ldcg1(const float* p) {
    float v;
    asm("ld.global.cg.f32 %0, [%1];" : "=f"(v) : "l"(p));
    return v;
}

// ---------------------------------------------------------------------------
// 1) Histogram of dst — 4 edges/thread (int4 load, 4 independent reductions)
// ---------------------------------------------------------------------------
__global__ void hist_kernel(const int* __restrict__ ei, int E) {
    int t = blockIdx.x * blockDim.x + threadIdx.x;
    int e = t * 4;
    if (e + 4 <= E) {
        int4 d = *(const int4*)&ei[E + e];
        atomicAdd(&g_cnt[d.x], 1);
        atomicAdd(&g_cnt[d.y], 1);
        atomicAdd(&g_cnt[d.z], 1);
        atomicAdd(&g_cnt[d.w], 1);
    } else {
        for (int k = e; k < E; k++) atomicAdd(&g_cnt[ei[E + k]], 1);
    }
}

// ---------------------------------------------------------------------------
// 2a) Local exclusive scan per 1024-chunk -> g_off (local), g_bsum[chunk]
// ---------------------------------------------------------------------------
__global__ void scan_local_kernel(int N) {
    __shared__ int wsum[32];
    int tid = threadIdx.x;
    int i = blockIdx.x * 1024 + tid;
    int v = (i < N) ? g_cnt[i] : 0;
    int lane = tid & 31, wid = tid >> 5;
    int s = v;
    #pragma unroll
    for (int o = 1; o < 32; o <<= 1) {
        int t = __shfl_up_sync(0xffffffffu, s, o);
        if (lane >= o) s += t;
    }
    if (lane == 31) wsum[wid] = s;
    __syncthreads();
    if (wid == 0) {
        int ws = wsum[lane];
        #pragma unroll
        for (int o = 1; o < 32; o <<= 1) {
            int t = __shfl_up_sync(0xffffffffu, ws, o);
            if (lane >= o) ws += t;
        }
        wsum[lane] = ws;
    }
    __syncthreads();
    int excl = s - v + (wid ? wsum[wid - 1] : 0);
    if (i < N) g_off[i] = excl;
    if (tid == 1023) g_bsum[blockIdx.x] = excl + v;
}

// ---------------------------------------------------------------------------
// 2b) Add chunk prefix, init cursors, write g_off[N], re-zero g_cnt.
// ---------------------------------------------------------------------------
__global__ void scan_add_kernel(int N, int nb) {
    __shared__ int pre;
    int i = blockIdx.x * 256 + threadIdx.x;
    if (threadIdx.x == 0) {
        int seg = (blockIdx.x * 256) >> 10;
        int acc = 0;
        for (int b = 0; b < seg; b++) acc += g_bsum[b];
        pre = acc;
    }
    __syncthreads();
    if (i < N) {
        int c = g_cnt[i];
        int o = g_off[i] + pre;
        g_off[i] = o;
        g_cursor[i] = o;
        g_cnt[i] = 0;                      // restore ZERO invariant
        if (i == N - 1) g_off[N] = o + c;  // total edge count
    }
}

// ---------------------------------------------------------------------------
// 3) Scatter src ids into dst-sorted order — 4 edges/thread
// ---------------------------------------------------------------------------
__global__ void sort_kernel(const int* __restrict__ ei, int E) {
    int t = blockIdx.x * blockDim.x + threadIdx.x;
    int e = t * 4;
    if (e + 4 <= E) {
        int4 s = *(const int4*)&ei[e];
        int4 d = *(const int4*)&ei[E + e];
        int p0 = atomicAdd(&g_cursor[d.x], 1);
        int p1 = atomicAdd(&g_cursor[d.y], 1);
        int p2 = atomicAdd(&g_cursor[d.z], 1);
        int p3 = atomicAdd(&g_cursor[d.w], 1);
        g_srcs[p0] = s.x;
        g_srcs[p1] = s.y;
        g_srcs[p2] = s.z;
        g_srcs[p3] = s.w;
    } else {
        for (int k = e; k < E; k++) {
            int pos = atomicAdd(&g_cursor[ei[E + k]], 1);
            g_srcs[pos] = ei[k];
        }
    }
}

// ---------------------------------------------------------------------------
// 4) GEMM h = x @ W^T + fused s_src/s_dst, packed f32x2 FFMA2 inner loop.
// ---------------------------------------------------------------------------
__global__ __launch_bounds__(256, 2) void gemm_s_kernel(
    const float* __restrict__ x, const float* __restrict__ W,
    const float* __restrict__ a, int N)
{
    extern __shared__ float sm[];
    float* XsT = sm;                  // 128 * 64   (XsT[k][r] = x[row0+r][k])
    float* Wt  = sm + 128 * 64;       // 128 * 132  (Wt[k][j]  = W[j][k])
    const int tid = threadIdx.x;
    const int tx = tid & 31;
    const int ty = tid >> 5;
    const int row0 = blockIdx.x * 64;

    const float4* W4 = (const float4*)W;
    for (int idx = tid; idx < D * (D / 4); idx += 256) {
        int j = idx >> 5;
        int k = (idx & 31) * 4;
        float4 w = W4[idx];
        Wt[(k + 0) * 132 + j] = w.x;
        Wt[(k + 1) * 132 + j] = w.y;
        Wt[(k + 2) * 132 + j] = w.z;
        Wt[(k + 3) * 132 + j] = w.w;
    }
    const float4* x4 = (const float4*)x;
    for (int idx = tid; idx < 64 * (D / 4); idx += 256) {
        int r = idx & 63;
        int k4 = idx >> 6;
        float4 v = make_float4(0.f, 0.f, 0.f, 0.f);
        if (row0 + r < N) v = x4[(row0 + r) * (D / 4) + k4];
        XsT[(k4 * 4 + 0) * 64 + r] = v.x;
        XsT[(k4 * 4 + 1) * 64 + r] = v.y;
        XsT[(k4 * 4 + 2) * 64 + r] = v.z;
        XsT[(k4 * 4 + 3) * 64 + r] = v.w;
    }
    __syncthreads();

    unsigned long long acc2[4][4];
    #pragma unroll
    for (int r2 = 0; r2 < 4; r2++)
        #pragma unroll
        for (int c = 0; c < 4; c++) acc2[r2][c] = dup2(0.f);

    #pragma unroll 4
    for (int k = 0; k < D; k++) {
        float4 wv = *(const float4*)&Wt[k * 132 + tx * 4];
        unsigned long long w0 = dup2(wv.x), w1 = dup2(wv.y);
        unsigned long long w2 = dup2(wv.z), w3 = dup2(wv.w);
        const float* xb = &XsT[k * 64 + ty * 8];
        #pragma unroll
        for (int r2 = 0; r2 < 4; r2++) {
            unsigned long long xx = *(const unsigned long long*)&xb[r2 * 2];
            fma2(acc2[r2][0], xx, w0);
            fma2(acc2[r2][1], xx, w1);
            fma2(acc2[r2][2], xx, w2);
            fma2(acc2[r2][3], xx, w3);
        }
    }

    float4 asrc = *(const float4*)&a[tx * 4];
    float4 adst = *(const float4*)&a[D + tx * 4];

    #pragma unroll
    for (int r2 = 0; r2 < 4; r2++) {
        float2 c0 = unpk2(acc2[r2][0]);
        float2 c1 = unpk2(acc2[r2][1]);
        float2 c2 = unpk2(acc2[r2][2]);
        float2 c3 = unpk2(acc2[r2][3]);
        #pragma unroll
        for (int half = 0; half < 2; half++) {
            int row = row0 + ty * 8 + r2 * 2 + half;
            if (row < N) {
                float4 hv = half == 0 ? make_float4(c0.x, c1.x, c2.x, c3.x)
                                      : make_float4(c0.y, c1.y, c2.y, c3.y);
                *(float4*)&g_h[row * D + tx * 4] = hv;
                float ps = hv.x * asrc.x + hv.y * asrc.y + hv.z * asrc.z + hv.w * asrc.w;
                float pd = hv.x * adst.x + hv.y * adst.y + hv.z * adst.z + hv.w * adst.w;
                #pragma unroll
                for (int off = 16; off > 0; off >>= 1) {
                    ps += __shfl_xor_sync(0xffffffffu, ps, off);
                    pd += __shfl_xor_sync(0xffffffffu, pd, off);
                }
                if (tx == 0) { g_ssrc[row] = ps; g_sdst[row] = pd; }
            }
        }
    }
}

// ---------------------------------------------------------------------------
// 5) Fused aggregate + residual + LayerNorm. One warp per dst node.
//    Always-unroll-4 with clamped-index + zero-weight predication: every edge
//    (including the tail) runs at MLP ~8 (4 h-rows + 4 ssrc in flight).
//    Gathers use ld.global.cg (L2-only; h is L2-resident, never L1-reused).
// ---------------------------------------------------------------------------
__global__ __launch_bounds__(256) void agg_ln_kernel(
    const float* __restrict__ x, const float* __restrict__ gamma,
    const float* __restrict__ beta, float* __restrict__ out, int N)
{
    int gw = (blockIdx.x * blockDim.x + threadIdx.x) >> 5;
    int lane = threadIdx.x & 31;
    if (gw >= N) return;
    int start = g_off[gw];
    int end = g_off[gw + 1];
    float sdst = g_sdst[gw];

    float a0 = 0.f, a1 = 0.f, a2 = 0.f, a3 = 0.f, z = 0.f;
    int last = end - 1;
    for (int e = start; e < end; e += 4) {
        int i0 = e;
        int i1 = min(e + 1, last);
        int i2 = min(e + 2, last);
        int i3 = min(e + 3, last);
        int s0 = __ldg(&g_srcs[i0]);
        int s1 = __ldg(&g_srcs[i1]);
        int s2 = __ldg(&g_srcs[i2]);
        int s3 = __ldg(&g_srcs[i3]);
        float4 h0 = ldcg4(&g_h[s0 * D + lane * 4]);
        float4 h1 = ldcg4(&g_h[s1 * D + lane * 4]);
        float4 h2 = ldcg4(&g_h[s2 * D + lane * 4]);
        float4 h3 = ldcg4(&g_h[s3 * D + lane * 4]);
        float v0 = ldcg1(&g_ssrc[s0]) + sdst; v0 = v0 > 0.f ? v0 : 0.2f * v0;
        float v1 = ldcg1(&g_ssrc[s1]) + sdst; v1 = v1 > 0.f ? v1 : 0.2f * v1;
        float v2 = ldcg1(&g_ssrc[s2]) + sdst; v2 = v2 > 0.f ? v2 : 0.2f * v2;
        float v3 = ldcg1(&g_ssrc[s3]) + sdst; v3 = v3 > 0.f ? v3 : 0.2f * v3;
        float e0 = __expf(v0);
        float e1 = (e + 1 < end) ? __expf(v1) : 0.f;
        float e2 = (e + 2 < end) ? __expf(v2) : 0.f;
        float e3 = (e + 3 < end) ? __expf(v3) : 0.f;
        z += (e0 + e1) + (e2 + e3);
        a0 += e0 * h0.x + e1 * h1.x + e2 * h2.x + e3 * h3.x;
        a1 += e0 * h0.y + e1 * h1.y + e2 * h2.y + e3 * h3.y;
        a2 += e0 * h0.z + e1 * h1.z + e2 * h2.z + e3 * h3.z;
        a3 += e0 * h0.w + e1 * h1.w + e2 * h2.w + e3 * h3.w;
    }
    float invz = (end > start) ? 1.f / z : 0.f;

    float4 xv = *(const float4*)&x[gw * D + lane * 4];
    float y0 = a0 * invz + xv.x, y1 = a1 * invz + xv.y;
    float y2 = a2 * invz + xv.z, y3 = a3 * invz + xv.w;

    float s = y0 + y1 + y2 + y3;
    #pragma unroll
    for (int off = 16; off > 0; off >>= 1) s += __shfl_xor_sync(0xffffffffu, s, off);
    float mean = s * (1.f / 128.f);
    float d0 = y0 - mean, d1 = y1 - mean, d2 = y2 - mean, d3 = y3 - mean;
    float q = d0 * d0 + d1 * d1 + d2 * d2 + d3 * d3;
    #pragma unroll
    for (int off = 16; off > 0; off >>= 1) q += __shfl_xor_sync(0xffffffffu, q, off);
    float inv = rsqrtf(q * (1.f / 128.f) + 1e-5f);

    float4 gv = *(const float4*)&gamma[lane * 4];
    float4 bv = *(const float4*)&beta[lane * 4];
    float4 o;
    o.x = d0 * inv * gv.x + bv.x;
    o.y = d1 * inv * gv.y + bv.y;
    o.z = d2 * inv * gv.z + bv.z;
    o.w = d3 * inv * gv.w + bv.w;
    *(float4*)&out[gw * D + lane * 4] = o;
}

// ---------------------------------------------------------------------------
// Launch: fork a side stream for the edge pipeline (depends only on
// edge_index), concurrent with the GEMM (depends only on x/W/a).
// ---------------------------------------------------------------------------
extern "C" void kernel_launch(void* const* d_in, const int* in_sizes, int n_in,
                              void* d_out, int out_size) {
    const float* x     = (const float*)d_in[0];
    const int*   ei    = (const int*)d_in[1];
    const float* W     = (const float*)d_in[2];
    const float* a     = (const float*)d_in[3];
    const float* gamma = (const float*)d_in[4];
    const float* beta  = (const float*)d_in[5];
    float* out = (float*)d_out;

    int N = in_sizes[0] / D;
    int E = in_sizes[1] / 2;
    int nb = (N + 1023) / 1024;
    int e4blocks = ((E + 3) / 4 + 255) / 256;

    static cudaStream_t s_side = nullptr;
    static cudaEvent_t ev_fork = nullptr, ev_join = nullptr;
    if (!s_side) {
        cudaStreamCreateWithFlags(&s_side, cudaStreamNonBlocking);
        cudaEventCreateWithFlags(&ev_fork, cudaEventDisableTiming);
        cudaEventCreateWithFlags(&ev_join, cudaEventDisableTiming);
    }

    int smem = (128 * 64 + 128 * 132) * (int)sizeof(float);  // ~98 KB
    cudaFuncSetAttribute(gemm_s_kernel, cudaFuncAttributeMaxDynamicSharedMemorySize, smem);

    cudaEventRecord(ev_fork, 0);
    cudaStreamWaitEvent(s_side, ev_fork, 0);
    hist_kernel<<<e4blocks, 256, 0, s_side>>>(ei, E);
    scan_local_kernel<<<nb, 1024, 0, s_side>>>(N);
    scan_add_kernel<<<(N + 255) / 256, 256, 0, s_side>>>(N, nb);
    sort_kernel<<<e4blocks, 256, 0, s_side>>>(ei, E);
    cudaEventRecord(ev_join, s_side);

    gemm_s_kernel<<<(N + 63) / 64, 256, smem>>>(x, W, a, N);

    cudaStreamWaitEvent(0, ev_join, 0);
    agg_ln_kernel<<<(N * 32 + 255) / 256, 256>>>(x, gamma, beta, out, N);
}

// round 6
// speedup vs baseline: 1.0581x; 1.0581x over previous
#include <cuda_runtime.h>
#include <cuda_fp16.h>

#define D 128
#define N_NODES_MAX 50000
#define E_MAX 600000

// Scratch (device globals — no allocation allowed)
__device__ __half2 g_hh[N_NODES_MAX * (D / 2)];  // h = x @ W^T, fp16 (gather payload)
__device__ float g_ssrc[N_NODES_MAX];       // h @ a[:128]  (fp32, from fp32 acc)
__device__ float g_sdst[N_NODES_MAX];       // h @ a[128:]
__device__ int   g_cnt[N_NODES_MAX];        // in-degree histogram (ZERO invariant: zeroed at
                                            // module load; re-zeroed by scan_add each call)
__device__ int   g_off[N_NODES_MAX + 1];    // CSR offsets (by dst)
__device__ int   g_cursor[N_NODES_MAX];     // scatter cursors
__device__ int   g_bsum[64];                // per-1024-chunk sums
__device__ int   g_srcs[E_MAX];             // src ids sorted by dst

// ---------------- packed f32x2 helpers (sm_103a FFMA2) ----------------
__device__ __forceinline__ unsigned long long dup2(float v) {
    unsigned long long r;
    asm("mov.b64 %0, {%1, %1};" : "=l"(r) : "f"(v));
    return r;
}
__device__ __forceinline__ void fma2(unsigned long long& d, unsigned long long a,
                                     unsigned long long b) {
    asm("fma.rn.f32x2 %0, %1, %2, %0;" : "+l"(d) : "l"(a), "l"(b));
}
__device__ __forceinline__ float2 unpk2(unsigned long long v) {
    float2 f;
    asm("mov.b64 {%0, %1}, %2;" : "=f"(f.x), "=f"(f.y) : "l"(v));
    return f;
}

// ---------------------------------------------------------------------------
// 1) Histogram of dst — 4 edges/thread
// ---------------------------------------------------------------------------
__global__ void hist_kernel(const int* __restrict__ ei, int E) {
    int t = blockIdx.x * blockDim.x + threadIdx.x;
    int e = t * 4;
    if (e + 4 <= E) {
        int4 d = *(const int4*)&ei[E + e];
        atomicAdd(&g_cnt[d.x], 1);
        atomicAdd(&g_cnt[d.y], 1);
        atomicAdd(&g_cnt[d.z], 1);
        atomicAdd(&g_cnt[d.w], 1);
    } else {
        for (int k = e; k < E; k++) atomicAdd(&g_cnt[ei[E + k]], 1);
    }
}

// ---------------------------------------------------------------------------
// 2a) Local exclusive scan per 1024-chunk -> g_off (local), g_bsum[chunk]
// ---------------------------------------------------------------------------
__global__ void scan_local_kernel(int N) {
    __shared__ int wsum[32];
    int tid = threadIdx.x;
    int i = blockIdx.x * 1024 + tid;
    int v = (i < N) ? g_cnt[i] : 0;
    int lane = tid & 31, wid = tid >> 5;
    int s = v;
    #pragma unroll
    for (int o = 1; o < 32; o <<= 1) {
        int t = __shfl_up_sync(0xffffffffu, s, o);
        if (lane >= o) s += t;
    }
    if (lane == 31) wsum[wid] = s;
    __syncthreads();
    if (wid == 0) {
        int ws = wsum[lane];
        #pragma unroll
        for (int o = 1; o < 32; o <<= 1) {
            int t = __shfl_up_sync(0xffffffffu, ws, o);
            if (lane >= o) ws += t;
        }
        wsum[lane] = ws;
    }
    __syncthreads();
    int excl = s - v + (wid ? wsum[wid - 1] : 0);
    if (i < N) g_off[i] = excl;
    if (tid == 1023) g_bsum[blockIdx.x] = excl + v;
}

// ---------------------------------------------------------------------------
// 2b) Add chunk prefix, init cursors, write g_off[N], re-zero g_cnt.
// ---------------------------------------------------------------------------
__global__ void scan_add_kernel(int N, int nb) {
    __shared__ int pre;
    int i = blockIdx.x * 256 + threadIdx.x;
    if (threadIdx.x == 0) {
        int seg = (blockIdx.x * 256) >> 10;
        int acc = 0;
        for (int b = 0; b < seg; b++) acc += g_bsum[b];
        pre = acc;
    }
    __syncthreads();
    if (i < N) {
        int c = g_cnt[i];
        int o = g_off[i] + pre;
        g_off[i] = o;
        g_cursor[i] = o;
        g_cnt[i] = 0;                      // restore ZERO invariant
        if (i == N - 1) g_off[N] = o + c;  // total edge count
    }
}

// ---------------------------------------------------------------------------
// 3) Scatter src ids into dst-sorted order — 4 edges/thread
// ---------------------------------------------------------------------------
__global__ void sort_kernel(const int* __restrict__ ei, int E) {
    int t = blockIdx.x * blockDim.x + threadIdx.x;
    int e = t * 4;
    if (e + 4 <= E) {
        int4 s = *(const int4*)&ei[e];
        int4 d = *(const int4*)&ei[E + e];
        int p0 = atomicAdd(&g_cursor[d.x], 1);
        int p1 = atomicAdd(&g_cursor[d.y], 1);
        int p2 = atomicAdd(&g_cursor[d.z], 1);
        int p3 = atomicAdd(&g_cursor[d.w], 1);
        g_srcs[p0] = s.x;
        g_srcs[p1] = s.y;
        g_srcs[p2] = s.z;
        g_srcs[p3] = s.w;
    } else {
        for (int k = e; k < E; k++) {
            int pos = atomicAdd(&g_cursor[ei[E + k]], 1);
            g_srcs[pos] = ei[k];
        }
    }
}

// ---------------------------------------------------------------------------
// 4) GEMM h = x @ W^T (fp32 accumulate, store h as fp16) + fused s_src/s_dst
//    (from fp32 accumulators). Packed f32x2 FFMA2 inner loop.
// ---------------------------------------------------------------------------
__global__ __launch_bounds__(256, 2) void gemm_s_kernel(
    const float* __restrict__ x, const float* __restrict__ W,
    const float* __restrict__ a, int N)
{
    extern __shared__ float sm[];
    float* XsT = sm;                  // 128 * 64   (XsT[k][r] = x[row0+r][k])
    float* Wt  = sm + 128 * 64;       // 128 * 132  (Wt[k][j]  = W[j][k])
    const int tid = threadIdx.x;
    const int tx = tid & 31;
    const int ty = tid >> 5;
    const int row0 = blockIdx.x * 64;

    const float4* W4 = (const float4*)W;
    for (int idx = tid; idx < D * (D / 4); idx += 256) {
        int j = idx >> 5;
        int k = (idx & 31) * 4;
        float4 w = W4[idx];
        Wt[(k + 0) * 132 + j] = w.x;
        Wt[(k + 1) * 132 + j] = w.y;
        Wt[(k + 2) * 132 + j] = w.z;
        Wt[(k + 3) * 132 + j] = w.w;
    }
    const float4* x4 = (const float4*)x;
    for (int idx = tid; idx < 64 * (D / 4); idx += 256) {
        int r = idx & 63;
        int k4 = idx >> 6;
        float4 v = make_float4(0.f, 0.f, 0.f, 0.f);
        if (row0 + r < N) v = x4[(row0 + r) * (D / 4) + k4];
        XsT[(k4 * 4 + 0) * 64 + r] = v.x;
        XsT[(k4 * 4 + 1) * 64 + r] = v.y;
        XsT[(k4 * 4 + 2) * 64 + r] = v.z;
        XsT[(k4 * 4 + 3) * 64 + r] = v.w;
    }
    __syncthreads();

    unsigned long long acc2[4][4];
    #pragma unroll
    for (int r2 = 0; r2 < 4; r2++)
        #pragma unroll
        for (int c = 0; c < 4; c++) acc2[r2][c] = dup2(0.f);

    #pragma unroll 4
    for (int k = 0; k < D; k++) {
        float4 wv = *(const float4*)&Wt[k * 132 + tx * 4];
        unsigned long long w0 = dup2(wv.x), w1 = dup2(wv.y);
        unsigned long long w2 = dup2(wv.z), w3 = dup2(wv.w);
        const float* xb = &XsT[k * 64 + ty * 8];
        #pragma unroll
        for (int r2 = 0; r2 < 4; r2++) {
            unsigned long long xx = *(const unsigned long long*)&xb[r2 * 2];
            fma2(acc2[r2][0], xx, w0);
            fma2(acc2[r2][1], xx, w1);
            fma2(acc2[r2][2], xx, w2);
            fma2(acc2[r2][3], xx, w3);
        }
    }

    float4 asrc = *(const float4*)&a[tx * 4];
    float4 adst = *(const float4*)&a[D + tx * 4];

    #pragma unroll
    for (int r2 = 0; r2 < 4; r2++) {
        float2 c0 = unpk2(acc2[r2][0]);
        float2 c1 = unpk2(acc2[r2][1]);
        float2 c2 = unpk2(acc2[r2][2]);
        float2 c3 = unpk2(acc2[r2][3]);
        #pragma unroll
        for (int half = 0; half < 2; half++) {
            int row = row0 + ty * 8 + r2 * 2 + half;
            if (row < N) {
                float4 hv = half == 0 ? make_float4(c0.x, c1.x, c2.x, c3.x)
                                      : make_float4(c0.y, c1.y, c2.y, c3.y);
                // store h as fp16 (half the gather payload)
                __half2 p01 = __floats2half2_rn(hv.x, hv.y);
                __half2 p23 = __floats2half2_rn(hv.z, hv.w);
                *(__half2*)&g_hh[row * (D / 2) + tx * 2 + 0] = p01;
                *(__half2*)&g_hh[row * (D / 2) + tx * 2 + 1] = p23;
                // scores from fp32 accumulators
                float ps = hv.x * asrc.x + hv.y * asrc.y + hv.z * asrc.z + hv.w * asrc.w;
                float pd = hv.x * adst.x + hv.y * adst.y + hv.z * adst.z + hv.w * adst.w;
                #pragma unroll
                for (int off = 16; off > 0; off >>= 1) {
                    ps += __shfl_xor_sync(0xffffffffu, ps, off);
                    pd += __shfl_xor_sync(0xffffffffu, pd, off);
                }
                if (tx == 0) { g_ssrc[row] = ps; g_sdst[row] = pd; }
            }
        }
    }
}

// ---------------------------------------------------------------------------
// 5) Fused aggregate + residual + LayerNorm. One warp per dst node, MLP=4,
//    fp16 h gather (8 B/lane/row), fp32 accumulation. Round-4 loop shape.
// ---------------------------------------------------------------------------
__global__ __launch_bounds__(256) void agg_ln_kernel(
    const float* __restrict__ x, const float* __restrict__ gamma,
    const float* __restrict__ beta, float* __restrict__ out, int N)
{
    int gw = (blockIdx.x * blockDim.x + threadIdx.x) >> 5;
    int lane = threadIdx.x & 31;
    if (gw >= N) return;
    int start = g_off[gw];
    int end = g_off[gw + 1];
    float sdst = g_sdst[gw];

    const __half2* hh = g_hh;
    float a0 = 0.f, a1 = 0.f, a2 = 0.f, a3 = 0.f, z = 0.f;
    int e = start;
    for (; e + 4 <= end; e += 4) {
        int s0 = g_srcs[e + 0];
        int s1 = g_srcs[e + 1];
        int s2 = g_srcs[e + 2];
        int s3 = g_srcs[e + 3];
        // 8 B per lane per row: two half2 loaded as one uint2
        uint2 r0 = *(const uint2*)&hh[s0 * (D / 2) + lane * 2];
        uint2 r1 = *(const uint2*)&hh[s1 * (D / 2) + lane * 2];
        uint2 r2 = *(const uint2*)&hh[s2 * (D / 2) + lane * 2];
        uint2 r3 = *(const uint2*)&hh[s3 * (D / 2) + lane * 2];
        float v0 = g_ssrc[s0] + sdst; v0 = v0 > 0.f ? v0 : 0.2f * v0;
        float v1 = g_ssrc[s1] + sdst; v1 = v1 > 0.f ? v1 : 0.2f * v1;
        float v2 = g_ssrc[s2] + sdst; v2 = v2 > 0.f ? v2 : 0.2f * v2;
        float v3 = g_ssrc[s3] + sdst; v3 = v3 > 0.f ? v3 : 0.2f * v3;
        float e0 = __expf(v0), e1 = __expf(v1), e2 = __expf(v2), e3 = __expf(v3);
        z += (e0 + e1) + (e2 + e3);
        float2 f0a = __half22float2(*(__half2*)&r0.x), f0b = __half22float2(*(__half2*)&r0.y);
        float2 f1a = __half22float2(*(__half2*)&r1.x), f1b = __half22float2(*(__half2*)&r1.y);
        float2 f2a = __half22float2(*(__half2*)&r2.x), f2b = __half22float2(*(__half2*)&r2.y);
        float2 f3a = __half22float2(*(__half2*)&r3.x), f3b = __half22float2(*(__half2*)&r3.y);
        a0 += e0 * f0a.x + e1 * f1a.x + e2 * f2a.x + e3 * f3a.x;
        a1 += e0 * f0a.y + e1 * f1a.y + e2 * f2a.y + e3 * f3a.y;
        a2 += e0 * f0b.x + e1 * f1b.x + e2 * f2b.x + e3 * f3b.x;
        a3 += e0 * f0b.y + e1 * f1b.y + e2 * f2b.y + e3 * f3b.y;
    }
    for (; e < end; e++) {
        int s0 = g_srcs[e];
        uint2 r0 = *(const uint2*)&hh[s0 * (D / 2) + lane * 2];
        float v0 = g_ssrc[s0] + sdst; v0 = v0 > 0.f ? v0 : 0.2f * v0;
        float e0 = __expf(v0);
        z += e0;
        float2 f0a = __half22float2(*(__half2*)&r0.x), f0b = __half22float2(*(__half2*)&r0.y);
        a0 += e0 * f0a.x; a1 += e0 * f0a.y; a2 += e0 * f0b.x; a3 += e0 * f0b.y;
    }
    float invz = (end > start) ? 1.f / z : 0.f;

    float4 xv = *(const float4*)&x[gw * D + lane * 4];
    float y0 = a0 * invz + xv.x, y1 = a1 * invz + xv.y;
    float y2 = a2 * invz + xv.z, y3 = a3 * invz + xv.w;

    float s = y0 + y1 + y2 + y3;
    #pragma unroll
    for (int off = 16; off > 0; off >>= 1) s += __shfl_xor_sync(0xffffffffu, s, off);
    float mean = s * (1.f / 128.f);
    float d0 = y0 - mean, d1 = y1 - mean, d2 = y2 - mean, d3 = y3 - mean;
    float q = d0 * d0 + d1 * d1 + d2 * d2 + d3 * d3;
    #pragma unroll
    for (int off = 16; off > 0; off >>= 1) q += __shfl_xor_sync(0xffffffffu, q, off);
    float inv = rsqrtf(q * (1.f / 128.f) + 1e-5f);

    float4 gv = *(const float4*)&gamma[lane * 4];
    float4 bv = *(const float4*)&beta[lane * 4];
    float4 o;
    o.x = d0 * inv * gv.x + bv.x;
    o.y = d1 * inv * gv.y + bv.y;
    o.z = d2 * inv * gv.z + bv.z;
    o.w = d3 * inv * gv.w + bv.w;
    *(float4*)&out[gw * D + lane * 4] = o;
}

// ---------------------------------------------------------------------------
// Launch: fork a side stream for the edge pipeline (depends only on
// edge_index), concurrent with the GEMM (depends only on x/W/a).
// ---------------------------------------------------------------------------
extern "C" void kernel_launch(void* const* d_in, const int* in_sizes, int n_in,
                              void* d_out, int out_size) {
    const float* x     = (const float*)d_in[0];
    const int*   ei    = (const int*)d_in[1];
    const float* W     = (const float*)d_in[2];
    const float* a     = (const float*)d_in[3];
    const float* gamma = (const float*)d_in[4];
    const float* beta  = (const float*)d_in[5];
    float* out = (float*)d_out;

    int N = in_sizes[0] / D;
    int E = in_sizes[1] / 2;
    int nb = (N + 1023) / 1024;
    int e4blocks = ((E + 3) / 4 + 255) / 256;

    static cudaStream_t s_side = nullptr;
    static cudaEvent_t ev_fork = nullptr, ev_join = nullptr;
    if (!s_side) {
        cudaStreamCreateWithFlags(&s_side, cudaStreamNonBlocking);
        cudaEventCreateWithFlags(&ev_fork, cudaEventDisableTiming);
        cudaEventCreateWithFlags(&ev_join, cudaEventDisableTiming);
    }

    int smem = (128 * 64 + 128 * 132) * (int)sizeof(float);  // ~98 KB
    cudaFuncSetAttribute(gemm_s_kernel, cudaFuncAttributeMaxDynamicSharedMemorySize, smem);

    cudaEventRecord(ev_fork, 0);
    cudaStreamWaitEvent(s_side, ev_fork, 0);
    hist_kernel<<<e4blocks, 256, 0, s_side>>>(ei, E);
    scan_local_kernel<<<nb, 1024, 0, s_side>>>(N);
    scan_add_kernel<<<(N + 255) / 256, 256, 0, s_side>>>(N, nb);
    sort_kernel<<<e4blocks, 256, 0, s_side>>>(ei, E);
    cudaEventRecord(ev_join, s_side);

    gemm_s_kernel<<<(N + 63) / 64, 256, smem>>>(x, W, a, N);

    cudaStreamWaitEvent(0, ev_join, 0);
    agg_ln_kernel<<<(N * 32 + 255) / 256, 256>>>(x, gamma, beta, out, N);
}

// round 9
// speedup vs baseline: 1.8842x; 1.7807x over previous
#include <cuda_runtime.h>
#include <cuda_fp16.h>
#include <cstdint>

#define D 128
#define N_NODES_MAX 50000
#define E_MAX 600000
#define AS_STRIDE 136   // fp16 elems per smem row (272B -> conflict-free ldmatrix)
#define HS_STRIDE 132   // fp16 elems per smem row for h staging (264B, 8B aligned)

// Scratch (device globals — no allocation allowed)
__device__ __half2 g_hh[N_NODES_MAX * (D / 2)];  // h = x @ W^T, fp16 (gather payload)
__device__ float g_ssrc[N_NODES_MAX];
__device__ float g_sdst[N_NODES_MAX];
__device__ int   g_cnt[N_NODES_MAX];        // ZERO invariant (module load; re-zeroed by scan_add)
__device__ int   g_off[N_NODES_MAX + 1];
__device__ int   g_cursor[N_NODES_MAX];
__device__ int   g_bsum[64];
__device__ int   g_srcs[E_MAX];

// ---------------- mma.sync helpers (builtin types only) ----------------
__device__ __forceinline__ void ldm4(unsigned int& r0, unsigned int& r1,
                                     unsigned int& r2, unsigned int& r3,
                                     const void* p) {
    unsigned int addr = (unsigned int)__cvta_generic_to_shared(p);
    asm volatile("ldmatrix.sync.aligned.m8n8.x4.shared.b16 {%0,%1,%2,%3}, [%4];"
                 : "=r"(r0), "=r"(r1), "=r"(r2), "=r"(r3) : "r"(addr));
}
__device__ __forceinline__ void mma16816(float* c, const unsigned int* a,
                                         const unsigned int* b) {
    asm volatile("mma.sync.aligned.m16n8k16.row.col.f32.f16.f16.f32 "
                 "{%0,%1,%2,%3}, {%4,%5,%6,%7}, {%8,%9}, {%0,%1,%2,%3};"
                 : "+f"(c[0]), "+f"(c[1]), "+f"(c[2]), "+f"(c[3])
                 : "r"(a[0]), "r"(a[1]), "r"(a[2]), "r"(a[3]), "r"(b[0]), "r"(b[1]));
}

// ---------------------------------------------------------------------------
// 1) Histogram of dst — 4 edges/thread
// ---------------------------------------------------------------------------
__global__ void hist_kernel(const int* __restrict__ ei, int E) {
    int t = blockIdx.x * blockDim.x + threadIdx.x;
    int e = t * 4;
    if (e + 4 <= E) {
        int4 d = *(const int4*)&ei[E + e];
        atomicAdd(&g_cnt[d.x], 1);
        atomicAdd(&g_cnt[d.y], 1);
        atomicAdd(&g_cnt[d.z], 1);
        atomicAdd(&g_cnt[d.w], 1);
    } else {
        for (int k = e; k < E; k++) atomicAdd(&g_cnt[ei[E + k]], 1);
    }
}

// ---------------------------------------------------------------------------
// 2a) Local exclusive scan per 1024-chunk
// ---------------------------------------------------------------------------
__global__ void scan_local_kernel(int N) {
    __shared__ int wsum[32];
    int tid = threadIdx.x;
    int i = blockIdx.x * 1024 + tid;
    int v = (i < N) ? g_cnt[i] : 0;
    int lane = tid & 31, wid = tid >> 5;
    int s = v;
    #pragma unroll
    for (int o = 1; o < 32; o <<= 1) {
        int t = __shfl_up_sync(0xffffffffu, s, o);
        if (lane >= o) s += t;
    }
    if (lane == 31) wsum[wid] = s;
    __syncthreads();
    if (wid == 0) {
        int ws = wsum[lane];
        #pragma unroll
        for (int o = 1; o < 32; o <<= 1) {
            int t = __shfl_up_sync(0xffffffffu, ws, o);
            if (lane >= o) ws += t;
        }
        wsum[lane] = ws;
    }
    __syncthreads();
    int excl = s - v + (wid ? wsum[wid - 1] : 0);
    if (i < N) g_off[i] = excl;
    if (tid == 1023) g_bsum[blockIdx.x] = excl + v;
}

// ---------------------------------------------------------------------------
// 2b) Add chunk prefix, init cursors, write g_off[N], re-zero g_cnt.
// ---------------------------------------------------------------------------
__global__ void scan_add_kernel(int N, int nb) {
    __shared__ int pre;
    int i = blockIdx.x * 256 + threadIdx.x;
    if (threadIdx.x == 0) {
        int seg = (blockIdx.x * 256) >> 10;
        int acc = 0;
        for (int b = 0; b < seg; b++) acc += g_bsum[b];
        pre = acc;
    }
    __syncthreads();
    if (i < N) {
        int c = g_cnt[i];
        int o = g_off[i] + pre;
        g_off[i] = o;
        g_cursor[i] = o;
        g_cnt[i] = 0;
        if (i == N - 1) g_off[N] = o + c;
    }
}

// ---------------------------------------------------------------------------
// 3) Scatter src ids into dst-sorted order — 4 edges/thread
// ---------------------------------------------------------------------------
__global__ void sort_kernel(const int* __restrict__ ei, int E) {
    int t = blockIdx.x * blockDim.x + threadIdx.x;
    int e = t * 4;
    if (e + 4 <= E) {
        int4 s = *(const int4*)&ei[e];
        int4 d = *(const int4*)&ei[E + e];
        int p0 = atomicAdd(&g_cursor[d.x], 1);
        int p1 = atomicAdd(&g_cursor[d.y], 1);
        int p2 = atomicAdd(&g_cursor[d.z], 1);
        int p3 = atomicAdd(&g_cursor[d.w], 1);
        g_srcs[p0] = s.x;
        g_srcs[p1] = s.y;
        g_srcs[p2] = s.z;
        g_srcs[p3] = s.w;
    } else {
        for (int k = e; k < E; k++) {
            int pos = atomicAdd(&g_cursor[ei[E + k]], 1);
            g_srcs[pos] = ei[k];
        }
    }
}

// ---------------------------------------------------------------------------
// 4) GEMM h = x @ W^T on tensor cores (mma.sync m16n8k16, fp16 in / fp32 acc).
//    CTA: 128 rows x 128 cols, 256 threads = 8 warps (4x2 grid, warp tile
//    32x64). Epilogue: h tile -> smem -> fp16 gmem (coalesced) + per-row
//    scores s_src/s_dst from the fp16 tile.
// ---------------------------------------------------------------------------
__global__ __launch_bounds__(256, 1) void gemm_mma_kernel(
    const float* __restrict__ x, const float* __restrict__ W,
    const float* __restrict__ a, int N)
{
    extern __shared__ __half sm2[];
    __half* As = sm2;                               // 128 x AS_STRIDE
    __half* Bs = sm2 + 128 * AS_STRIDE;             // 128 x AS_STRIDE (W rows: [n][k])
    float* a_s = (float*)(sm2 + 2 * 128 * AS_STRIDE);  // 256 floats
    const int tid = threadIdx.x;
    const int row0 = blockIdx.x * 128;

    a_s[tid] = a[tid];

    // Stage x tile + W, fp32 -> fp16, coalesced global float4 reads.
    const float4* x4 = (const float4*)x;
    const float4* W4 = (const float4*)W;
    #pragma unroll
    for (int i = 0; i < 16; i++) {
        int idx = tid + i * 256;          // 0..4095
        int k4 = idx & 31, r = idx >> 5;
        float4 v = (row0 + r < N) ? x4[(row0 + r) * 32 + k4]
                                  : make_float4(0.f, 0.f, 0.f, 0.f);
        *(__half2*)&As[r * AS_STRIDE + k4 * 4]     = __floats2half2_rn(v.x, v.y);
        *(__half2*)&As[r * AS_STRIDE + k4 * 4 + 2] = __floats2half2_rn(v.z, v.w);
        float4 w = W4[idx];
        *(__half2*)&Bs[r * AS_STRIDE + k4 * 4]     = __floats2half2_rn(w.x, w.y);
        *(__half2*)&Bs[r * AS_STRIDE + k4 * 4 + 2] = __floats2half2_rn(w.z, w.w);
    }
    __syncthreads();

    const int wid = tid >> 5, lane = tid & 31;
    const int m_base = (wid & 3) * 32;
    const int n_base = (wid >> 2) * 64;

    float acc[2][8][4];
    #pragma unroll
    for (int tm = 0; tm < 2; tm++)
        #pragma unroll
        for (int tn = 0; tn < 8; tn++)
            #pragma unroll
            for (int c = 0; c < 4; c++) acc[tm][tn][c] = 0.f;

    // ldmatrix lane address components
    const int lmA = (lane & 7) + ((lane >> 3) & 1) * 8;  // m within 16
    const int lkA = (lane >> 4) * 8;                     // k offset 0/8
    const int lnB = (lane & 7) + (lane >> 4) * 8;        // n within 16
    const int lkB = ((lane >> 3) & 1) * 8;               // k offset 0/8

    #pragma unroll
    for (int ks = 0; ks < 8; ks++) {
        int k0 = ks * 16;
        unsigned int af[2][4];
        #pragma unroll
        for (int tm = 0; tm < 2; tm++)
            ldm4(af[tm][0], af[tm][1], af[tm][2], af[tm][3],
                 &As[(m_base + tm * 16 + lmA) * AS_STRIDE + k0 + lkA]);
        unsigned int bf[8][2];
        #pragma unroll
        for (int tp = 0; tp < 4; tp++) {
            unsigned int r0, r1, r2, r3;
            ldm4(r0, r1, r2, r3,
                 &Bs[(n_base + tp * 16 + lnB) * AS_STRIDE + k0 + lkB]);
            bf[tp * 2][0] = r0; bf[tp * 2][1] = r1;
            bf[tp * 2 + 1][0] = r2; bf[tp * 2 + 1][1] = r3;
        }
        #pragma unroll
        for (int tm = 0; tm < 2; tm++)
            #pragma unroll
            for (int tn = 0; tn < 8; tn++)
                mma16816(acc[tm][tn], af[tm], bf[tn]);
    }

    // Epilogue: stage fp16 h tile in smem (reuse As region).
    __syncthreads();
    __half* Hs = As;   // 128 x HS_STRIDE
    #pragma unroll
    for (int tm = 0; tm < 2; tm++) {
        int m = m_base + tm * 16 + (lane >> 2);
        #pragma unroll
        for (int tn = 0; tn < 8; tn++) {
            int n = n_base + tn * 8 + (lane & 3) * 2;
            *(__half2*)&Hs[m * HS_STRIDE + n] =
                __floats2half2_rn(acc[tm][tn][0], acc[tm][tn][1]);
            *(__half2*)&Hs[(m + 8) * HS_STRIDE + n] =
                __floats2half2_rn(acc[tm][tn][2], acc[tm][tn][3]);
        }
    }
    __syncthreads();

    // Coalesced fp16 h writeback: 128 rows x 32 uint2
    #pragma unroll
    for (int i = 0; i < 16; i++) {
        int idx = tid + i * 256;      // 0..4095
        int c = idx & 31, r = idx >> 5;
        if (row0 + r < N) {
            uint2 v = *(uint2*)&Hs[r * HS_STRIDE + c * 4];
            *(uint2*)&g_hh[(row0 + r) * 64 + c * 2] = v;
        }
    }

    // Scores: threads 0-127 -> s_src rows, 128-255 -> s_dst rows.
    {
        int r = tid & 127;
        const float* av = a_s + ((tid >= 128) ? 128 : 0);
        if (row0 + r < N) {
            float s = 0.f;
            #pragma unroll 8
            for (int j = 0; j < 64; j++) {
                float2 f = __half22float2(*(__half2*)&Hs[r * HS_STRIDE + j * 2]);
                s += f.x * av[2 * j] + f.y * av[2 * j + 1];
            }
            if (tid >= 128) g_sdst[row0 + r] = s;
            else            g_ssrc[row0 + r] = s;
        }
    }
}

// ---------------------------------------------------------------------------
// 5) Fused aggregate + residual + LayerNorm (R6 shape, fp16 gather).
// ---------------------------------------------------------------------------
__global__ __launch_bounds__(256) void agg_ln_kernel(
    const float* __restrict__ x, const float* __restrict__ gamma,
    const float* __restrict__ beta, float* __restrict__ out, int N)
{
    int gw = (blockIdx.x * blockDim.x + threadIdx.x) >> 5;
    int lane = threadIdx.x & 31;
    if (gw >= N) return;
    int start = g_off[gw];
    int end = g_off[gw + 1];
    float sdst = g_sdst[gw];

    const __half2* hh = g_hh;
    float a0 = 0.f, a1 = 0.f, a2 = 0.f, a3 = 0.f, z = 0.f;
    int e = start;
    for (; e + 4 <= end; e += 4) {
        int s0 = g_srcs[e + 0];
        int s1 = g_srcs[e + 1];
        int s2 = g_srcs[e + 2];
        int s3 = g_srcs[e + 3];
        uint2 r0 = *(const uint2*)&hh[s0 * (D / 2) + lane * 2];
        uint2 r1 = *(const uint2*)&hh[s1 * (D / 2) + lane * 2];
        uint2 r2 = *(const uint2*)&hh[s2 * (D / 2) + lane * 2];
        uint2 r3 = *(const uint2*)&hh[s3 * (D / 2) + lane * 2];
        float v0 = g_ssrc[s0] + sdst; v0 = v0 > 0.f ? v0 : 0.2f * v0;
        float v1 = g_ssrc[s1] + sdst; v1 = v1 > 0.f ? v1 : 0.2f * v1;
        float v2 = g_ssrc[s2] + sdst; v2 = v2 > 0.f ? v2 : 0.2f * v2;
        float v3 = g_ssrc[s3] + sdst; v3 = v3 > 0.f ? v3 : 0.2f * v3;
        float e0 = __expf(v0), e1 = __expf(v1), e2 = __expf(v2), e3 = __expf(v3);
        z += (e0 + e1) + (e2 + e3);
        float2 f0a = __half22float2(*(__half2*)&r0.x), f0b = __half22float2(*(__half2*)&r0.y);
        float2 f1a = __half22float2(*(__half2*)&r1.x), f1b = __half22float2(*(__half2*)&r1.y);
        float2 f2a = __half22float2(*(__half2*)&r2.x), f2b = __half22float2(*(__half2*)&r2.y);
        float2 f3a = __half22float2(*(__half2*)&r3.x), f3b = __half22float2(*(__half2*)&r3.y);
        a0 += e0 * f0a.x + e1 * f1a.x + e2 * f2a.x + e3 * f3a.x;
        a1 += e0 * f0a.y + e1 * f1a.y + e2 * f2a.y + e3 * f3a.y;
        a2 += e0 * f0b.x + e1 * f1b.x + e2 * f2b.x + e3 * f3b.x;
        a3 += e0 * f0b.y + e1 * f1b.y + e2 * f2b.y + e3 * f3b.y;
    }
    for (; e < end; e++) {
        int s0 = g_srcs[e];
        uint2 r0 = *(const uint2*)&hh[s0 * (D / 2) + lane * 2];
        float v0 = g_ssrc[s0] + sdst; v0 = v0 > 0.f ? v0 : 0.2f * v0;
        float e0 = __expf(v0);
        z += e0;
        float2 f0a = __half22float2(*(__half2*)&r0.x), f0b = __half22float2(*(__half2*)&r0.y);
        a0 += e0 * f0a.x; a1 += e0 * f0a.y; a2 += e0 * f0b.x; a3 += e0 * f0b.y;
    }
    float invz = (end > start) ? 1.f / z : 0.f;

    float4 xv = *(const float4*)&x[gw * D + lane * 4];
    float y0 = a0 * invz + xv.x, y1 = a1 * invz + xv.y;
    float y2 = a2 * invz + xv.z, y3 = a3 * invz + xv.w;

    float s = y0 + y1 + y2 + y3;
    #pragma unroll
    for (int off = 16; off > 0; off >>= 1) s += __shfl_xor_sync(0xffffffffu, s, off);
    float mean = s * (1.f / 128.f);
    float d0 = y0 - mean, d1 = y1 - mean, d2 = y2 - mean, d3 = y3 - mean;
    float q = d0 * d0 + d1 * d1 + d2 * d2 + d3 * d3;
    #pragma unroll
    for (int off = 16; off > 0; off >>= 1) q += __shfl_xor_sync(0xffffffffu, q, off);
    float inv = rsqrtf(q * (1.f / 128.f) + 1e-5f);

    float4 gv = *(const float4*)&gamma[lane * 4];
    float4 bv = *(const float4*)&beta[lane * 4];
    float4 o;
    o.x = d0 * inv * gv.x + bv.x;
    o.y = d1 * inv * gv.y + bv.y;
    o.z = d2 * inv * gv.z + bv.z;
    o.w = d3 * inv * gv.w + bv.w;
    *(float4*)&out[gw * D + lane * 4] = o;
}

// ---------------------------------------------------------------------------
extern "C" void kernel_launch(void* const* d_in, const int* in_sizes, int n_in,
                              void* d_out, int out_size) {
    const float* x     = (const float*)d_in[0];
    const int*   ei    = (const int*)d_in[1];
    const float* W     = (const float*)d_in[2];
    const float* a     = (const float*)d_in[3];
    const float* gamma = (const float*)d_in[4];
    const float* beta  = (const float*)d_in[5];
    float* out = (float*)d_out;

    int N = in_sizes[0] / D;
    int E = in_sizes[1] / 2;
    int nb = (N + 1023) / 1024;
    int e4blocks = ((E + 3) / 4 + 255) / 256;

    static cudaStream_t s_side = nullptr;
    static cudaEvent_t ev_fork = nullptr, ev_join = nullptr;
    if (!s_side) {
        cudaStreamCreateWithFlags(&s_side, cudaStreamNonBlocking);
        cudaEventCreateWithFlags(&ev_fork, cudaEventDisableTiming);
        cudaEventCreateWithFlags(&ev_join, cudaEventDisableTiming);
    }

    int smem = 2 * 128 * AS_STRIDE * (int)sizeof(__half) + 256 * (int)sizeof(float); // ~70.7KB
    cudaFuncSetAttribute(gemm_mma_kernel, cudaFuncAttributeMaxDynamicSharedMemorySize, smem);

    cudaEventRecord(ev_fork, 0);
    cudaStreamWaitEvent(s_side, ev_fork, 0);
    hist_kernel<<<e4blocks, 256, 0, s_side>>>(ei, E);
    scan_local_kernel<<<nb, 1024, 0, s_side>>>(N);
    scan_add_kernel<<<(N + 255) / 256, 256, 0, s_side>>>(N, nb);
    sort_kernel<<<e4blocks, 256, 0, s_side>>>(ei, E);
    cudaEventRecord(ev_join, s_side);

    gemm_mma_kernel<<<(N + 127) / 128, 256, smem>>>(x, W, a, N);

    cudaStreamWaitEvent(0, ev_join, 0);
    agg_ln_kernel<<<(N * 32 + 255) / 256, 256>>>(x, gamma, beta, out, N);
}